// round 5
// baseline (speedup 1.0000x reference)
#include <cuda_runtime.h>
#include <cuda_bf16.h>
#include <cstdint>

// ---------------------------------------------------------------------------
// PPEG: out = dwconv7(x) + x + dwconv5(x) + dwconv3(x)  (depthwise, per-channel)
// Folded into ONE 7x7x7 depthwise conv per channel + combined bias.
// Each thread computes 2 adjacent h-outputs: a loaded d-column at row dh'
// feeds output A (dh=dh') and output B (dh=dh'-1)  -> ~43% fewer LDS.64.
// Even-dd taps: packed fma.rn.f32x2 on aligned float2 pairs; odd-dd: scalar.
//
// x layout  (per channel c): volume[d][h][w], d=16, h=64, w=64 (w contiguous)
// out layout(per channel c): [h][w][d] with d contiguous (stride-1)
// ---------------------------------------------------------------------------

#define NCH   512
#define DD    16
#define HH    64
#define WW    64
#define VOL   (DD*HH*WW)      // 65536 per channel

#define WSTRIDE 352           // per-channel slot in g_wcomb (343 taps + bias)
__device__ float g_wcomb[NCH * WSTRIDE];

typedef unsigned long long u64;
typedef unsigned int u32;

// packed FMA building the a-operand from two scalar float regs (ptxas aliases
// the pair when they already live in an even/odd pair from LDS.64)
#define FMA2P(acc_, alo_, ahi_, w2_) \
    asm("{\n\t.reg .b64 _a;\n\tmov.b64 _a, {%1, %2};\n\t" \
        "fma.rn.f32x2 %0, _a, %3, %0;\n\t}" \
        : "+l"(acc_) : "f"(alo_), "f"(ahi_), "l"(w2_))

// -------------------- weight folding --------------------
__global__ void fold_weights_kernel(const float* __restrict__ w7,
                                    const float* __restrict__ b7,
                                    const float* __restrict__ w5,
                                    const float* __restrict__ b5,
                                    const float* __restrict__ w3,
                                    const float* __restrict__ b3) {
    int c = blockIdx.x;
    for (int t = threadIdx.x; t < 343; t += blockDim.x) {
        int dd = t / 49;
        int r  = t % 49;
        int dh = r / 7;
        int dw = r % 7;
        float v = w7[c * 343 + t];
        if (dd >= 1 && dd <= 5 && dh >= 1 && dh <= 5 && dw >= 1 && dw <= 5)
            v += w5[c * 125 + (dd - 1) * 25 + (dh - 1) * 5 + (dw - 1)];
        if (dd >= 2 && dd <= 4 && dh >= 2 && dh <= 4 && dw >= 2 && dw <= 4)
            v += w3[c * 27 + (dd - 2) * 9 + (dh - 2) * 3 + (dw - 2)];
        if (t == 171) v += 1.0f;   // identity: center tap (3,3,3)
        g_wcomb[c * WSTRIDE + t] = v;
    }
    if (threadIdx.x == 0)
        g_wcomb[c * WSTRIDE + 343] = b7[c] + b5[c] + b3[c];
}

// -------------------- main conv --------------------
// CTA: one channel, 4 consecutive h rows, full W, full D.  128 threads.
// Thread (w, hq): outputs at h = h0+2hq and h0+2hq+1, 16 d-values each.
// Smem tile d-innermost: [sh=10][sw=70][sd_pad=26], halo 3 each side, zero-padded.
#define SM_D  22
#define SDP   26
#define SM_H  10
#define SM_W  70
#define NCOLS (SM_H * SM_W)                  // 700 (sh,sw) columns
#define TILE_FLOATS (NCOLS * SDP)            // 18200
#define SMEM_BYTES  (TILE_FLOATS * 4 + 343 * 8 + 8)
#define NTHR  128

// apply all 7 dd taps of one (dh,dw) weight column to one accumulator bank
__device__ __forceinline__ void acc_taps(const float2 zv[11], const u64* __restrict__ wrow,
                                         int dw, u64 accE[8], float accO[16]) {
#pragma unroll
    for (int s = 0; s < 4; ++s) {            // even dd = 2s, packed
        const u64 w2 = wrow[(2 * s) * 49 + dw];
#pragma unroll
        for (int j = 0; j < 8; ++j)
            FMA2P(accE[j], zv[j + s].x, zv[j + s].y, w2);
    }
#pragma unroll
    for (int s = 0; s < 3; ++s) {            // odd dd = 2s+1, scalar
        const float wv = ((const float*)&wrow[(2 * s + 1) * 49 + dw])[0];
#pragma unroll
        for (int o = 0; o < 16; ++o) {
            const int k = o + 2 * s + 1;
            const float zk = (k & 1) ? zv[k >> 1].y : zv[k >> 1].x;
            accO[o] = fmaf(zk, wv, accO[o]);
        }
    }
}

__device__ __forceinline__ void store16(float* out, size_t base,
                                        const u64 accE[8], const float accO[16]) {
    float res[16];
#pragma unroll
    for (int j = 0; j < 8; ++j) {
        float lo, hi;
        asm("mov.b64 {%0, %1}, %2;" : "=f"(lo), "=f"(hi) : "l"(accE[j]));
        res[2 * j]     = accO[2 * j]     + lo;
        res[2 * j + 1] = accO[2 * j + 1] + hi;
    }
    float4* op = (float4*)(out + base);
    op[0] = make_float4(res[0],  res[1],  res[2],  res[3]);
    op[1] = make_float4(res[4],  res[5],  res[6],  res[7]);
    op[2] = make_float4(res[8],  res[9],  res[10], res[11]);
    op[3] = make_float4(res[12], res[13], res[14], res[15]);
}

__global__ __launch_bounds__(NTHR, 3)
void ppeg_conv_kernel(const float* __restrict__ x, float* __restrict__ out) {
    extern __shared__ float smem[];
    float* sx  = smem;                        // transposed input tile
    u64*  swt2 = (u64*)(smem + TILE_FLOATS);  // 343 duplicated (w,w) weight pairs
    float* sbias = (float*)(swt2 + 343);

    const int c   = blockIdx.y;
    const int h0  = blockIdx.x * 4;
    const int tid = threadIdx.x;

    const float* __restrict__ xc = x + (size_t)c * VOL;

    // folded weights for this channel, duplicated into (w,w) pairs
    for (int i = tid; i < 343; i += NTHR) {
        float wv = g_wcomb[c * WSTRIDE + i];
        ((float2*)swt2)[i] = make_float2(wv, wv);
    }
    if (tid == 0) sbias[0] = g_wcomb[c * WSTRIDE + 343];

    // ---- tile load: one (sh,sw) column of 22 d-values per iteration ----
    for (int col = tid; col < NCOLS; col += NTHR) {
        int sh = col / SM_W;
        int sw = col - sh * SM_W;
        int gh = h0 + sh - 3;
        int gw = sw - 3;
        bool okhw = ((unsigned)gh < (unsigned)HH) && ((unsigned)gw < (unsigned)WW);
        const float* gp = xc + (gh * WW + gw);

        float z[SM_D];
#pragma unroll
        for (int sd = 0; sd < SM_D; ++sd) {
            int gd = sd - 3;
            float v = 0.0f;
            if (gd >= 0 && gd < DD)            // compile-time predicate
                v = okhw ? __ldg(gp + gd * (HH * WW)) : 0.0f;
            z[sd] = v;
        }

        float2* sp = (float2*)(sx + col * SDP);
#pragma unroll
        for (int m = 0; m < 11; ++m)
            sp[m] = make_float2(z[2 * m], z[2 * m + 1]);
    }
    __syncthreads();

    const int w  = tid & 63;   // 0..63
    const int hq = tid >> 6;   // 0..1  -> outputs at h0+2hq (A), h0+2hq+1 (B)

    const float bias = sbias[0];
    u64   accE_A[8], accE_B[8];
    float accO_A[16], accO_B[16];
#pragma unroll
    for (int j = 0; j < 8; ++j) { accE_A[j] = 0ull; accE_B[j] = 0ull; }
#pragma unroll
    for (int o = 0; o < 16; ++o) { accO_A[o] = bias; accO_B[o] = bias; }

    const int shbase = 2 * hq;

    // dh' = 0: feeds A only (dh=0)
    {
        const float* rowbase = sx + ((shbase + 0) * SM_W + w) * SDP;
#pragma unroll
        for (int dw = 0; dw < 7; ++dw) {
            float2 zv[11];
            const float2* col2 = (const float2*)(rowbase + dw * SDP);
#pragma unroll
            for (int m = 0; m < 11; ++m) zv[m] = col2[m];
            acc_taps(zv, swt2 + 0 * 7, dw, accE_A, accO_A);
        }
    }

    // dh' = 1..6: feeds A (dh=dh') and B (dh=dh'-1)
#pragma unroll 1
    for (int dhp = 1; dhp < 7; ++dhp) {
        const float* rowbase = sx + ((shbase + dhp) * SM_W + w) * SDP;
        const u64* wrA = swt2 + dhp * 7;
        const u64* wrB = swt2 + (dhp - 1) * 7;
#pragma unroll
        for (int dw = 0; dw < 7; ++dw) {
            float2 zv[11];
            const float2* col2 = (const float2*)(rowbase + dw * SDP);
#pragma unroll
            for (int m = 0; m < 11; ++m) zv[m] = col2[m];
            acc_taps(zv, wrA, dw, accE_A, accO_A);
            acc_taps(zv, wrB, dw, accE_B, accO_B);
        }
    }

    // dh' = 7: feeds B only (dh=6)
    {
        const float* rowbase = sx + ((shbase + 7) * SM_W + w) * SDP;
#pragma unroll
        for (int dw = 0; dw < 7; ++dw) {
            float2 zv[11];
            const float2* col2 = (const float2*)(rowbase + dw * SDP);
#pragma unroll
            for (int m = 0; m < 11; ++m) zv[m] = col2[m];
            acc_taps(zv, swt2 + 6 * 7, dw, accE_B, accO_B);
        }
    }

    // store: out[c][(h*64+w)*16 + d]
    const size_t cb = (size_t)c * VOL;
    store16(out, cb + ((size_t)(h0 + shbase)     * WW + w) * 16, accE_A, accO_A);
    store16(out, cb + ((size_t)(h0 + shbase + 1) * WW + w) * 16, accE_B, accO_B);
}

// -------------------- launch --------------------
extern "C" void kernel_launch(void* const* d_in, const int* in_sizes, int n_in,
                              void* d_out, int out_size) {
    const float* x  = (const float*)d_in[0];
    const float* w7 = (const float*)d_in[1];
    const float* b7 = (const float*)d_in[2];
    const float* w5 = (const float*)d_in[3];
    const float* b5 = (const float*)d_in[4];
    const float* w3 = (const float*)d_in[5];
    const float* b3 = (const float*)d_in[6];
    float* out = (float*)d_out;

    fold_weights_kernel<<<NCH, 256>>>(w7, b7, w5, b5, w3, b3);

    static bool attr_set = false;
    if (!attr_set) {
        cudaFuncSetAttribute(ppeg_conv_kernel,
                             cudaFuncAttributeMaxDynamicSharedMemorySize, SMEM_BYTES);
        attr_set = true;
    }

    dim3 grid(HH / 4, NCH);   // 16 h-tiles x 512 channels
    ppeg_conv_kernel<<<grid, NTHR, SMEM_BYTES>>>(x, out);
}

// round 6
// speedup vs baseline: 1.0251x; 1.0251x over previous
#include <cuda_runtime.h>
#include <cuda_bf16.h>
#include <cstdint>

// ---------------------------------------------------------------------------
// PPEG: out = dwconv7(x) + x + dwconv5(x) + dwconv3(x)  (depthwise, per-channel)
// Folded into ONE 7x7x7 depthwise conv per channel + combined bias.
// Thread computes 2 adjacent h-outputs (d-column loaded once feeds dh and dh-1).
// Even-dd taps: packed fma.rn.f32x2 on aligned float2 pairs; odd-dd: scalar.
// 256-thread CTA covers 8 h-rows -> 2 CTAs/SM, 16 warps (restores occupancy).
//
// x layout  (per channel c): volume[d][h][w], d=16, h=64, w=64 (w contiguous)
// out layout(per channel c): [h][w][d] with d contiguous (stride-1)
// ---------------------------------------------------------------------------

#define NCH   512
#define DD    16
#define HH    64
#define WW    64
#define VOL   (DD*HH*WW)      // 65536 per channel

#define WSTRIDE 352           // per-channel slot in g_wcomb (343 taps + bias)
__device__ float g_wcomb[NCH * WSTRIDE];

typedef unsigned long long u64;
typedef unsigned int u32;

#define FMA2P(acc_, alo_, ahi_, w2_) \
    asm("{\n\t.reg .b64 _a;\n\tmov.b64 _a, {%1, %2};\n\t" \
        "fma.rn.f32x2 %0, _a, %3, %0;\n\t}" \
        : "+l"(acc_) : "f"(alo_), "f"(ahi_), "l"(w2_))

// -------------------- weight folding --------------------
__global__ void fold_weights_kernel(const float* __restrict__ w7,
                                    const float* __restrict__ b7,
                                    const float* __restrict__ w5,
                                    const float* __restrict__ b5,
                                    const float* __restrict__ w3,
                                    const float* __restrict__ b3) {
    int c = blockIdx.x;
    for (int t = threadIdx.x; t < 343; t += blockDim.x) {
        int dd = t / 49;
        int r  = t % 49;
        int dh = r / 7;
        int dw = r % 7;
        float v = w7[c * 343 + t];
        if (dd >= 1 && dd <= 5 && dh >= 1 && dh <= 5 && dw >= 1 && dw <= 5)
            v += w5[c * 125 + (dd - 1) * 25 + (dh - 1) * 5 + (dw - 1)];
        if (dd >= 2 && dd <= 4 && dh >= 2 && dh <= 4 && dw >= 2 && dw <= 4)
            v += w3[c * 27 + (dd - 2) * 9 + (dh - 2) * 3 + (dw - 2)];
        if (t == 171) v += 1.0f;   // identity: center tap (3,3,3)
        g_wcomb[c * WSTRIDE + t] = v;
    }
    if (threadIdx.x == 0)
        g_wcomb[c * WSTRIDE + 343] = b7[c] + b5[c] + b3[c];
}

// -------------------- main conv --------------------
// CTA: one channel, 8 consecutive h rows, full W, full D.  256 threads.
// Thread (w, hq): outputs at h = h0+2hq and h0+2hq+1, 16 d-values each.
// Smem tile d-innermost: [sh=14][sw=70][sd_pad=26], halo 3 each side, zero-padded.
#define SM_D  22
#define SDP   26
#define SM_H  14
#define SM_W  70
#define NCOLS (SM_H * SM_W)                  // 980 (sh,sw) columns
#define TILE_FLOATS (NCOLS * SDP)            // 25480
#define SMEM_BYTES  (TILE_FLOATS * 4 + 343 * 8 + 8)   // ~104.7 KB
#define NTHR  256

// apply all 7 dd taps of one (dh,dw) weight column to one accumulator bank
__device__ __forceinline__ void acc_taps(const float2 zv[11], const u64* __restrict__ wrow,
                                         int dw, u64 accE[8], float accO[16]) {
#pragma unroll
    for (int s = 0; s < 4; ++s) {            // even dd = 2s, packed
        const u64 w2 = wrow[(2 * s) * 49 + dw];
#pragma unroll
        for (int j = 0; j < 8; ++j)
            FMA2P(accE[j], zv[j + s].x, zv[j + s].y, w2);
    }
#pragma unroll
    for (int s = 0; s < 3; ++s) {            // odd dd = 2s+1, scalar
        const float wv = ((const float*)&wrow[(2 * s + 1) * 49 + dw])[0];
#pragma unroll
        for (int o = 0; o < 16; ++o) {
            const int k = o + 2 * s + 1;
            const float zk = (k & 1) ? zv[k >> 1].y : zv[k >> 1].x;
            accO[o] = fmaf(zk, wv, accO[o]);
        }
    }
}

__device__ __forceinline__ void store16(float* out, size_t base,
                                        const u64 accE[8], const float accO[16]) {
    float res[16];
#pragma unroll
    for (int j = 0; j < 8; ++j) {
        float lo, hi;
        asm("mov.b64 {%0, %1}, %2;" : "=f"(lo), "=f"(hi) : "l"(accE[j]));
        res[2 * j]     = accO[2 * j]     + lo;
        res[2 * j + 1] = accO[2 * j + 1] + hi;
    }
    float4* op = (float4*)(out + base);
    op[0] = make_float4(res[0],  res[1],  res[2],  res[3]);
    op[1] = make_float4(res[4],  res[5],  res[6],  res[7]);
    op[2] = make_float4(res[8],  res[9],  res[10], res[11]);
    op[3] = make_float4(res[12], res[13], res[14], res[15]);
}

__global__ __launch_bounds__(NTHR, 2)
void ppeg_conv_kernel(const float* __restrict__ x, float* __restrict__ out) {
    extern __shared__ float smem[];
    float* sx  = smem;                        // transposed input tile
    u64*  swt2 = (u64*)(smem + TILE_FLOATS);  // 343 duplicated (w,w) weight pairs
    float* sbias = (float*)(swt2 + 343);

    const int c   = blockIdx.y;
    const int h0  = blockIdx.x * 8;
    const int tid = threadIdx.x;

    const float* __restrict__ xc = x + (size_t)c * VOL;

    // folded weights for this channel, duplicated into (w,w) pairs
    for (int i = tid; i < 343; i += NTHR) {
        float wv = g_wcomb[c * WSTRIDE + i];
        ((float2*)swt2)[i] = make_float2(wv, wv);
    }
    if (tid == 0) sbias[0] = g_wcomb[c * WSTRIDE + 343];

    // ---- tile load: one (sh,sw) column of 22 d-values per iteration ----
    for (int col = tid; col < NCOLS; col += NTHR) {
        int sh = col / SM_W;
        int sw = col - sh * SM_W;
        int gh = h0 + sh - 3;
        int gw = sw - 3;
        bool okhw = ((unsigned)gh < (unsigned)HH) && ((unsigned)gw < (unsigned)WW);
        const float* gp = xc + (gh * WW + gw);

        float z[SM_D];
#pragma unroll
        for (int sd = 0; sd < SM_D; ++sd) {
            int gd = sd - 3;
            float v = 0.0f;
            if (gd >= 0 && gd < DD)            // compile-time predicate
                v = okhw ? __ldg(gp + gd * (HH * WW)) : 0.0f;
            z[sd] = v;
        }

        float2* sp = (float2*)(sx + col * SDP);
#pragma unroll
        for (int m = 0; m < 11; ++m)
            sp[m] = make_float2(z[2 * m], z[2 * m + 1]);
    }
    __syncthreads();

    const int w  = tid & 63;   // 0..63
    const int hq = tid >> 6;   // 0..3  -> outputs at h0+2hq (A), h0+2hq+1 (B)

    const float bias = sbias[0];
    u64   accE_A[8], accE_B[8];
    float accO_A[16], accO_B[16];
#pragma unroll
    for (int j = 0; j < 8; ++j) { accE_A[j] = 0ull; accE_B[j] = 0ull; }
#pragma unroll
    for (int o = 0; o < 16; ++o) { accO_A[o] = bias; accO_B[o] = bias; }

    const int shbase = 2 * hq;

    // dh' = 0: feeds A only (dh=0)
    {
        const float* rowbase = sx + ((shbase + 0) * SM_W + w) * SDP;
#pragma unroll
        for (int dw = 0; dw < 7; ++dw) {
            float2 zv[11];
            const float2* col2 = (const float2*)(rowbase + dw * SDP);
#pragma unroll
            for (int m = 0; m < 11; ++m) zv[m] = col2[m];
            acc_taps(zv, swt2 + 0 * 7, dw, accE_A, accO_A);
        }
    }

    // dh' = 1..6: feeds A (dh=dh') and B (dh=dh'-1)
#pragma unroll 1
    for (int dhp = 1; dhp < 7; ++dhp) {
        const float* rowbase = sx + ((shbase + dhp) * SM_W + w) * SDP;
        const u64* wrA = swt2 + dhp * 7;
        const u64* wrB = swt2 + (dhp - 1) * 7;
#pragma unroll
        for (int dw = 0; dw < 7; ++dw) {
            float2 zv[11];
            const float2* col2 = (const float2*)(rowbase + dw * SDP);
#pragma unroll
            for (int m = 0; m < 11; ++m) zv[m] = col2[m];
            acc_taps(zv, wrA, dw, accE_A, accO_A);
            acc_taps(zv, wrB, dw, accE_B, accO_B);
        }
    }

    // dh' = 7: feeds B only (dh=6)
    {
        const float* rowbase = sx + ((shbase + 7) * SM_W + w) * SDP;
#pragma unroll
        for (int dw = 0; dw < 7; ++dw) {
            float2 zv[11];
            const float2* col2 = (const float2*)(rowbase + dw * SDP);
#pragma unroll
            for (int m = 0; m < 11; ++m) zv[m] = col2[m];
            acc_taps(zv, swt2 + 6 * 7, dw, accE_B, accO_B);
        }
    }

    // store: out[c][(h*64+w)*16 + d]
    const size_t cb = (size_t)c * VOL;
    store16(out, cb + ((size_t)(h0 + shbase)     * WW + w) * 16, accE_A, accO_A);
    store16(out, cb + ((size_t)(h0 + shbase + 1) * WW + w) * 16, accE_B, accO_B);
}

// -------------------- launch --------------------
extern "C" void kernel_launch(void* const* d_in, const int* in_sizes, int n_in,
                              void* d_out, int out_size) {
    const float* x  = (const float*)d_in[0];
    const float* w7 = (const float*)d_in[1];
    const float* b7 = (const float*)d_in[2];
    const float* w5 = (const float*)d_in[3];
    const float* b5 = (const float*)d_in[4];
    const float* w3 = (const float*)d_in[5];
    const float* b3 = (const float*)d_in[6];
    float* out = (float*)d_out;

    fold_weights_kernel<<<NCH, 256>>>(w7, b7, w5, b5, w3, b3);

    static bool attr_set = false;
    if (!attr_set) {
        cudaFuncSetAttribute(ppeg_conv_kernel,
                             cudaFuncAttributeMaxDynamicSharedMemorySize, SMEM_BYTES);
        attr_set = true;
    }

    dim3 grid(HH / 8, NCH);   // 8 h-tiles x 512 channels
    ppeg_conv_kernel<<<grid, NTHR, SMEM_BYTES>>>(x, out);
}

// round 7
// speedup vs baseline: 1.0377x; 1.0123x over previous
#include <cuda_runtime.h>
#include <cuda_bf16.h>
#include <cstdint>

// ---------------------------------------------------------------------------
// PPEG: out = dwconv7(x) + x + dwconv5(x) + dwconv3(x)  (depthwise, per-channel)
// Folded into ONE 7x7x7 depthwise conv per channel + combined bias.
// Thread computes 2 adjacent h-outputs (dh-reuse). ALL dd taps packed f32x2:
//   even dd -> aligned output pairs (0,1)(2,3)... ; odd dd -> staggered pairs
//   (1,2)(3,4)...(13,14) whose inputs are ALSO aligned zv pairs, + 2 scalars.
// Columns loaded with LDS.128 (SDP=28, conflict-free, 16B aligned).
//
// x layout  (per channel c): volume[d][h][w], d=16, h=64, w=64 (w contiguous)
// out layout(per channel c): [h][w][d] with d contiguous (stride-1)
// ---------------------------------------------------------------------------

#define NCH   512
#define DD    16
#define HH    64
#define WW    64
#define VOL   (DD*HH*WW)      // 65536 per channel

#define WSTRIDE 352           // per-channel slot in g_wcomb (343 taps + bias)
__device__ float g_wcomb[NCH * WSTRIDE];

typedef unsigned long long u64;
typedef unsigned int u32;

#define FMA2P(acc_, alo_, ahi_, w2_) \
    asm("{\n\t.reg .b64 _a;\n\tmov.b64 _a, {%1, %2};\n\t" \
        "fma.rn.f32x2 %0, _a, %3, %0;\n\t}" \
        : "+l"(acc_) : "f"(alo_), "f"(ahi_), "l"(w2_))

// -------------------- weight folding --------------------
__global__ void fold_weights_kernel(const float* __restrict__ w7,
                                    const float* __restrict__ b7,
                                    const float* __restrict__ w5,
                                    const float* __restrict__ b5,
                                    const float* __restrict__ w3,
                                    const float* __restrict__ b3) {
    int c = blockIdx.x;
    for (int t = threadIdx.x; t < 343; t += blockDim.x) {
        int dd = t / 49;
        int r  = t % 49;
        int dh = r / 7;
        int dw = r % 7;
        float v = w7[c * 343 + t];
        if (dd >= 1 && dd <= 5 && dh >= 1 && dh <= 5 && dw >= 1 && dw <= 5)
            v += w5[c * 125 + (dd - 1) * 25 + (dh - 1) * 5 + (dw - 1)];
        if (dd >= 2 && dd <= 4 && dh >= 2 && dh <= 4 && dw >= 2 && dw <= 4)
            v += w3[c * 27 + (dd - 2) * 9 + (dh - 2) * 3 + (dw - 2)];
        if (t == 171) v += 1.0f;   // identity: center tap (3,3,3)
        g_wcomb[c * WSTRIDE + t] = v;
    }
    if (threadIdx.x == 0)
        g_wcomb[c * WSTRIDE + 343] = b7[c] + b5[c] + b3[c];
}

// -------------------- main conv --------------------
// CTA: one channel, 8 consecutive h rows, full W, full D.  256 threads.
// Thread (w, hq): outputs at h = h0+2hq and h0+2hq+1, 16 d-values each.
// Smem tile d-innermost: [sh=14][sw=70][sd_pad=28], halo 3 each side, zero-padded.
// Column stride 28 words: LDS.128 8-lane phases hit distinct bank-quads (7l mod 8).
#define SM_D  22
#define SDP   28
#define SM_H  14
#define SM_W  70
#define NCOLS (SM_H * SM_W)                  // 980 (sh,sw) columns
#define TILE_FLOATS (NCOLS * SDP)            // 27440
#define SMEM_BYTES  (TILE_FLOATS * 4 + 343 * 8 + 8)   // ~112.5 KB
#define NTHR  256

struct AccBank {
    u64   E[8];   // even-dd: pairs (out0,out1)..(out14,out15), bias pre-added
    u64   Q[7];   // odd-dd:  pairs (out1,out2)..(out13,out14)
    float s0;     // odd-dd scalar for out0
    float s15;    // odd-dd scalar for out15
};

__device__ __forceinline__ void bank_init(AccBank& a, u64 bias2) {
#pragma unroll
    for (int j = 0; j < 8; ++j) a.E[j] = bias2;
#pragma unroll
    for (int j = 0; j < 7; ++j) a.Q[j] = 0ull;
    a.s0 = 0.0f; a.s15 = 0.0f;
}

// apply all 7 dd taps of one (dh,dw) weight column to one accumulator bank
__device__ __forceinline__ void acc_taps(const float2* zv, const u64* __restrict__ wrow,
                                         int dw, AccBank& a) {
#pragma unroll
    for (int s = 0; s < 4; ++s) {            // even dd = 2s
        const u64 w2 = wrow[(2 * s) * 49 + dw];
#pragma unroll
        for (int j = 0; j < 8; ++j)
            FMA2P(a.E[j], zv[j + s].x, zv[j + s].y, w2);
    }
#pragma unroll
    for (int s = 0; s < 3; ++s) {            // odd dd = 2s+1
        const u64 w2 = wrow[(2 * s + 1) * 49 + dw];
        const float wv = ((const float*)wrow)[(2 * s + 1) * 98 + 2 * dw];
#pragma unroll
        for (int j = 0; j < 7; ++j)          // Q_j inputs: zv[j+s+1] (aligned!)
            FMA2P(a.Q[j], zv[j + s + 1].x, zv[j + s + 1].y, w2);
        a.s0  = fmaf(zv[s].y,     wv, a.s0);   // out0:  z[2s+1]
        a.s15 = fmaf(zv[8 + s].x, wv, a.s15);  // out15: z[16+2s]
    }
}

__device__ __forceinline__ void store16(float* out, size_t base, const AccBank& a) {
    float e[16], q[14];
#pragma unroll
    for (int j = 0; j < 8; ++j)
        asm("mov.b64 {%0, %1}, %2;" : "=f"(e[2*j]), "=f"(e[2*j+1]) : "l"(a.E[j]));
#pragma unroll
    for (int j = 0; j < 7; ++j)
        asm("mov.b64 {%0, %1}, %2;" : "=f"(q[2*j]), "=f"(q[2*j+1]) : "l"(a.Q[j]));
    float res[16];
    res[0]  = e[0]  + a.s0;
    res[15] = e[15] + a.s15;
#pragma unroll
    for (int j = 0; j < 7; ++j) {
        res[2*j + 1] = e[2*j + 1] + q[2*j];       // out[2j+1] = E.hi + Q[j].lo
        res[2*j + 2] = e[2*j + 2] + q[2*j + 1];   // out[2j+2] = E.lo + Q[j].hi
    }
    float4* op = (float4*)(out + base);
    op[0] = make_float4(res[0],  res[1],  res[2],  res[3]);
    op[1] = make_float4(res[4],  res[5],  res[6],  res[7]);
    op[2] = make_float4(res[8],  res[9],  res[10], res[11]);
    op[3] = make_float4(res[12], res[13], res[14], res[15]);
}

__global__ __launch_bounds__(NTHR, 2)
void ppeg_conv_kernel(const float* __restrict__ x, float* __restrict__ out) {
    extern __shared__ float smem[];
    float* sx  = smem;                        // transposed input tile
    u64*  swt2 = (u64*)(smem + TILE_FLOATS);  // 343 duplicated (w,w) weight pairs
    float* sbias = (float*)(swt2 + 343);

    const int c   = blockIdx.y;
    const int h0  = blockIdx.x * 8;
    const int tid = threadIdx.x;

    const float* __restrict__ xc = x + (size_t)c * VOL;

    // folded weights for this channel, duplicated into (w,w) pairs
    for (int i = tid; i < 343; i += NTHR) {
        float wv = g_wcomb[c * WSTRIDE + i];
        ((float2*)swt2)[i] = make_float2(wv, wv);
    }
    if (tid == 0) sbias[0] = g_wcomb[c * WSTRIDE + 343];

    // ---- tile load: one (sh,sw) column of 22 d-values per iteration ----
    for (int col = tid; col < NCOLS; col += NTHR) {
        int sh = col / SM_W;
        int sw = col - sh * SM_W;
        int gh = h0 + sh - 3;
        int gw = sw - 3;
        bool okhw = ((unsigned)gh < (unsigned)HH) && ((unsigned)gw < (unsigned)WW);
        const float* gp = xc + (gh * WW + gw);

        float z[24];
#pragma unroll
        for (int sd = 0; sd < 24; ++sd) {
            int gd = sd - 3;
            float v = 0.0f;
            if (gd >= 0 && gd < DD)            // compile-time predicate
                v = okhw ? __ldg(gp + gd * (HH * WW)) : 0.0f;
            z[sd] = v;
        }

        float4* sp = (float4*)(sx + col * SDP);   // 16B aligned (28*4 % 16 == 0)
#pragma unroll
        for (int m = 0; m < 6; ++m)
            sp[m] = make_float4(z[4*m], z[4*m+1], z[4*m+2], z[4*m+3]);
    }
    __syncthreads();

    const int w  = tid & 63;   // 0..63
    const int hq = tid >> 6;   // 0..3  -> outputs at h0+2hq (A), h0+2hq+1 (B)

    u64 bias2;
    {
        float b = sbias[0];
        asm("mov.b64 %0, {%1, %2};" : "=l"(bias2) : "f"(b), "f"(b));
    }
    AccBank A, B;
    bank_init(A, bias2);
    bank_init(B, bias2);

    const int shbase = 2 * hq;

    // dh' = 0: feeds A only (dh=0)
    {
        const float* rowbase = sx + ((shbase + 0) * SM_W + w) * SDP;
#pragma unroll
        for (int dw = 0; dw < 7; ++dw) {
            float4 zf[6];
            const float4* col4 = (const float4*)(rowbase + dw * SDP);
#pragma unroll
            for (int m = 0; m < 6; ++m) zf[m] = col4[m];
            acc_taps((const float2*)zf, swt2 + 0 * 7, dw, A);
        }
    }

    // dh' = 1..6: feeds A (dh=dh') and B (dh=dh'-1)
#pragma unroll 1
    for (int dhp = 1; dhp < 7; ++dhp) {
        const float* rowbase = sx + ((shbase + dhp) * SM_W + w) * SDP;
        const u64* wrA = swt2 + dhp * 7;
        const u64* wrB = swt2 + (dhp - 1) * 7;
#pragma unroll
        for (int dw = 0; dw < 7; ++dw) {
            float4 zf[6];
            const float4* col4 = (const float4*)(rowbase + dw * SDP);
#pragma unroll
            for (int m = 0; m < 6; ++m) zf[m] = col4[m];
            acc_taps((const float2*)zf, wrA, dw, A);
            acc_taps((const float2*)zf, wrB, dw, B);
        }
    }

    // dh' = 7: feeds B only (dh=6)
    {
        const float* rowbase = sx + ((shbase + 7) * SM_W + w) * SDP;
#pragma unroll
        for (int dw = 0; dw < 7; ++dw) {
            float4 zf[6];
            const float4* col4 = (const float4*)(rowbase + dw * SDP);
#pragma unroll
            for (int m = 0; m < 6; ++m) zf[m] = col4[m];
            acc_taps((const float2*)zf, swt2 + 6 * 7, dw, B);
        }
    }

    // store: out[c][(h*64+w)*16 + d]
    const size_t cb = (size_t)c * VOL;
    store16(out, cb + ((size_t)(h0 + shbase)     * WW + w) * 16, A);
    store16(out, cb + ((size_t)(h0 + shbase + 1) * WW + w) * 16, B);
}

// -------------------- launch --------------------
extern "C" void kernel_launch(void* const* d_in, const int* in_sizes, int n_in,
                              void* d_out, int out_size) {
    const float* x  = (const float*)d_in[0];
    const float* w7 = (const float*)d_in[1];
    const float* b7 = (const float*)d_in[2];
    const float* w5 = (const float*)d_in[3];
    const float* b5 = (const float*)d_in[4];
    const float* w3 = (const float*)d_in[5];
    const float* b3 = (const float*)d_in[6];
    float* out = (float*)d_out;

    fold_weights_kernel<<<NCH, 256>>>(w7, b7, w5, b5, w3, b3);

    static bool attr_set = false;
    if (!attr_set) {
        cudaFuncSetAttribute(ppeg_conv_kernel,
                             cudaFuncAttributeMaxDynamicSharedMemorySize, SMEM_BYTES);
        attr_set = true;
    }

    dim3 grid(HH / 8, NCH);   // 8 h-tiles x 512 channels
    ppeg_conv_kernel<<<grid, NTHR, SMEM_BYTES>>>(x, out);
}